// round 9
// baseline (speedup 1.0000x reference)
#include <cuda_runtime.h>
#include <cstddef>

#define N_NODES 100000
#define N_EDGES 1600000
#define IN_CH   128
#define HEADS   4
#define OUT_CH  32
#define F_TOT   128   // HEADS*OUT_CH
#define MAX_SLOTS 256
#define SLOTS_PER_WARP 8

// Scratch (static __device__ allocation; runtime alloc forbidden)
__device__ float    g_proj[(size_t)N_NODES * F_TOT];   // 51.2 MB
__device__ float    g_norm[(size_t)N_NODES * HEADS];   // 1.6 MB
__device__ unsigned g_slot[HEADS * MAX_SLOTS];         // hashed per-head max slots
__device__ float    g_hmax[HEADS];                     // final per-head max
__device__ int      g_cnt[N_NODES];                    // in-degree histogram
__device__ int      g_off[N_NODES + 1];                // CSR offsets
__device__ int      g_cur[N_NODES];                    // scatter cursors
__device__ int      g_ebuf[N_EDGES];                   // src index per CSR slot
__device__ int      g_cbuf[N_EDGES];                   // dst (col) index per CSR slot

// monotone float->uint map (order-preserving); inverse for readback
__device__ __forceinline__ unsigned fmap(float f) {
    unsigned u = __float_as_uint(f);
    return (u & 0x80000000u) ? ~u : (u | 0x80000000u);
}
__device__ __forceinline__ float funmap(unsigned u) {
    return __uint_as_float((u & 0x80000000u) ? (u & 0x7FFFFFFFu) : ~u);
}

// fast tanh: 2 MUFU + few FMA; rel err ~1e-6 (validated: pipeline rel_err 3.7e-7)
__device__ __forceinline__ float fast_tanh(float x) {
    float ax = fabsf(x);
    float e  = __expf(2.0f * ax);             // inf for large ax -> r = 1
    float r  = 1.0f - __fdividef(2.0f, e + 1.0f);
    return copysignf(r, x);
}

// ---------------------------------------------------------------------------
// GEMM: proj = x @ W   ([100000,128] @ [128,128])  (unchanged, known-good)
// ---------------------------------------------------------------------------
__global__ __launch_bounds__(256) void gemm_kernel(const float* __restrict__ x,
                                                   const float* __restrict__ Wm) {
    __shared__ float xs[64][16];
    __shared__ float ws[16][128];
    const int t  = threadIdx.x;
    const int tx = t & 15;
    const int ty = t >> 4;
    const int rowBase = blockIdx.x * 64;

    float acc[4][8];
#pragma unroll
    for (int i = 0; i < 4; i++)
#pragma unroll
        for (int j = 0; j < 8; j++) acc[i][j] = 0.f;

    const int lr = t >> 2;
    const int lk = (t & 3) * 4;
    int gr = rowBase + lr;
    if (gr >= N_NODES) gr = N_NODES - 1;

    for (int kk = 0; kk < IN_CH; kk += 16) {
        *(float4*)&xs[lr][lk] =
            *(const float4*)(x + (size_t)gr * IN_CH + kk + lk);
#pragma unroll
        for (int rep = 0; rep < 2; rep++) {
            int idx = t + rep * 256;
            int k   = idx >> 5;
            int c4  = (idx & 31) * 4;
            *(float4*)&ws[k][c4] =
                *(const float4*)(Wm + (size_t)(kk + k) * F_TOT + c4);
        }
        __syncthreads();
#pragma unroll
        for (int k = 0; k < 16; k++) {
            float4 b0 = *(float4*)&ws[k][tx * 8];
            float4 b1 = *(float4*)&ws[k][tx * 8 + 4];
#pragma unroll
            for (int i = 0; i < 4; i++) {
                float a = xs[ty * 4 + i][k];
                acc[i][0] += a * b0.x; acc[i][1] += a * b0.y;
                acc[i][2] += a * b0.z; acc[i][3] += a * b0.w;
                acc[i][4] += a * b1.x; acc[i][5] += a * b1.y;
                acc[i][6] += a * b1.z; acc[i][7] += a * b1.w;
            }
        }
        __syncthreads();
    }

#pragma unroll
    for (int i = 0; i < 4; i++) {
        int r = rowBase + ty * 4 + i;
        if (r < N_NODES) {
            *(float4*)(g_proj + (size_t)r * F_TOT + tx * 8) =
                make_float4(acc[i][0], acc[i][1], acc[i][2], acc[i][3]);
            *(float4*)(g_proj + (size_t)r * F_TOT + tx * 8 + 4) =
                make_float4(acc[i][4], acc[i][5], acc[i][6], acc[i][7]);
        }
    }
}

// ---------------------------------------------------------------------------
// CSR build (hist -> scan -> scatter); scatter stores BOTH src and col
// ---------------------------------------------------------------------------
__global__ __launch_bounds__(256) void hist_kernel(const int* __restrict__ ei) {
    int e = blockIdx.x * blockDim.x + threadIdx.x;
    if (e < N_EDGES) atomicAdd(&g_cnt[ei[N_EDGES + e]], 1);
}

__global__ __launch_bounds__(1024) void scan_kernel() {
    __shared__ int part[1024];
    const int t  = threadIdx.x;
    const int CH = (N_NODES + 1023) / 1024;   // 98
    const int base = t * CH;

    int s = 0;
    for (int i = 0; i < CH; i++) {
        int idx = base + i;
        if (idx < N_NODES) s += g_cnt[idx];
    }
    part[t] = s;
    __syncthreads();
    for (int off = 1; off < 1024; off <<= 1) {
        int v = (t >= off) ? part[t - off] : 0;
        __syncthreads();
        part[t] += v;
        __syncthreads();
    }
    int run = (t == 0) ? 0 : part[t - 1];
    for (int i = 0; i < CH; i++) {
        int idx = base + i;
        if (idx < N_NODES) {
            g_off[idx] = run;
            g_cur[idx] = run;
            run += g_cnt[idx];
        }
    }
    if (t == 0) g_off[N_NODES] = N_EDGES;
}

__global__ __launch_bounds__(256) void scatter_kernel(const int* __restrict__ ei) {
    int e = blockIdx.x * blockDim.x + threadIdx.x;
    if (e < N_EDGES) {
        int col = ei[N_EDGES + e];
        int row = ei[e];
        int pos = atomicAdd(&g_cur[col], 1);
        g_ebuf[pos] = row;
        g_cbuf[pos] = col;
    }
}

// ---------------------------------------------------------------------------
// Walk kernel v2 — two-phase. One warp per 8 consecutive CSR slots (perfect
// balance, 200000 warps). PHASE 1: all 8 scores computed with no stores/
// branches: 8 independent load->tanh->shfl->exp chains, fully unrolled ->
// compiler pipelines them. Dst row loaded blindly per slot; consecutive
// slots share the column so L1 dedups (dup loads never reach LTS).
// PHASE 2: segmented flush; red.v4 + norm atomic only at column boundaries
// (~2.3 per warp) -> LTS traffic ~1.24 GB vs 2.5 GB edge-parallel.
// ---------------------------------------------------------------------------
__device__ __forceinline__ void red_v4(float* p, float4 v) {
    asm volatile("red.global.add.v4.f32 [%0], {%1,%2,%3,%4};"
                 :: "l"(p), "f"(v.x), "f"(v.y), "f"(v.z), "f"(v.w));
}

__global__ __launch_bounds__(256) void walk_kernel(const float* __restrict__ att,
                                                   float* __restrict__ out) {
    const int warp = (blockIdx.x * blockDim.x + threadIdx.x) >> 5;  // 200000
    const int lane = threadIdx.x & 31;
    const int base = warp * SLOTS_PER_WARP;   // exact fit

    const float4 a4 = *(const float4*)(att + lane * 4);

    int srcs[SLOTS_PER_WARP], cols[SLOTS_PER_WARP];
#pragma unroll
    for (int k = 0; k < SLOTS_PER_WARP; k++) {
        srcs[k] = g_ebuf[base + k];
        cols[k] = g_cbuf[base + k];
    }

    // ---------------- phase 1: pure compute, 8 independent chains ---------
    float4 s[SLOTS_PER_WARP];
    float  w[SLOTS_PER_WARP];
    float  pmax = -3.4e38f;
#pragma unroll
    for (int k = 0; k < SLOTS_PER_WARP; k++) {
        s[k] = *(const float4*)(g_proj + (size_t)srcs[k] * F_TOT + lane * 4);
        const float4 d = *(const float4*)(g_proj + (size_t)cols[k] * F_TOT + lane * 4);
        float p = fast_tanh(s[k].x + d.x) * a4.x
                + fast_tanh(s[k].y + d.y) * a4.y
                + fast_tanh(s[k].z + d.z) * a4.z
                + fast_tanh(s[k].w + d.w) * a4.w;
        p += __shfl_xor_sync(0xffffffffu, p, 4);
        p += __shfl_xor_sync(0xffffffffu, p, 2);
        p += __shfl_xor_sync(0xffffffffu, p, 1);
        w[k] = __expf(p);
        pmax = fmaxf(pmax, p);
    }

    // ---------------- phase 2: segmented flush ----------------------------
    float4 acc  = make_float4(0.f, 0.f, 0.f, 0.f);
    float  nacc = 0.f;
#pragma unroll
    for (int k = 0; k < SLOTS_PER_WARP; k++) {
        acc.x += s[k].x * w[k]; acc.y += s[k].y * w[k];
        acc.z += s[k].z * w[k]; acc.w += s[k].w * w[k];
        nacc += w[k];
        const bool flush = (k == SLOTS_PER_WARP - 1) || (cols[k + 1] != cols[k]);
        if (flush) {            // warp-uniform (cols identical across lanes)
            red_v4(out + (size_t)cols[k] * F_TOT + lane * 4, acc);
            if ((lane & 7) == 0)
                atomicAdd(g_norm + (size_t)cols[k] * HEADS + (lane >> 3), nacc);
            acc  = make_float4(0.f, 0.f, 0.f, 0.f);
            nacc = 0.f;
        }
    }

    if ((lane & 7) == 0)
        atomicMax(&g_slot[(lane >> 3) * MAX_SLOTS + (warp & (MAX_SLOTS - 1))],
                  fmap(pmax));
}

// ---------------------------------------------------------------------------
// Reduce hashed max slots -> g_hmax[h]
// ---------------------------------------------------------------------------
__global__ __launch_bounds__(256) void maxreduce_kernel() {
    __shared__ unsigned sm[256];
    const int t = threadIdx.x;
    for (int h = 0; h < HEADS; h++) {
        sm[t] = g_slot[h * MAX_SLOTS + t];
        __syncthreads();
        for (int s = 128; s > 0; s >>= 1) {
            if (t < s) sm[t] = max(sm[t], sm[t + s]);
            __syncthreads();
        }
        if (t == 0) g_hmax[h] = funmap(sm[0]);
        __syncthreads();
    }
}

// ---------------------------------------------------------------------------
// Finalize: exact reference semantics including the 1e-12 clamp:
//   scale = exp(-max_h); out = out_acc*scale / max(norm_acc*scale, 1e-12)
// ---------------------------------------------------------------------------
__global__ __launch_bounds__(256) void finalize_kernel(float* __restrict__ out) {
    size_t i4 = (size_t)blockIdx.x * blockDim.x + threadIdx.x;
    if (i4 >= (size_t)N_NODES * (F_TOT / 4)) return;
    int n = (int)(i4 >> 5);
    int q = (int)(i4 & 31);
    int h = q >> 3;
    float scale = __expf(-g_hmax[h]);
    float nr    = g_norm[(size_t)n * HEADS + h] * scale;
    float inv   = scale / fmaxf(nr, 1e-12f);
    float4 v = *(float4*)(out + i4 * 4);
    v.x *= inv; v.y *= inv; v.z *= inv; v.w *= inv;
    *(float4*)(out + i4 * 4) = v;
}

// ---------------------------------------------------------------------------
extern "C" void kernel_launch(void* const* d_in, const int* in_sizes, int n_in,
                              void* d_out, int out_size) {
    const float* x   = (const float*)d_in[0];
    const int*   ei  = (const int*)d_in[1];    // int32 edge_index [2, E]
    const float* Wm  = (const float*)d_in[2];
    const float* att = (const float*)d_in[3];
    float*       out = (float*)d_out;

    void* cntPtr  = nullptr;
    void* slotPtr = nullptr;
    void* normPtr = nullptr;
    cudaGetSymbolAddress(&cntPtr, g_cnt);
    cudaGetSymbolAddress(&slotPtr, g_slot);
    cudaGetSymbolAddress(&normPtr, g_norm);

    cudaMemsetAsync(out, 0, (size_t)N_NODES * F_TOT * sizeof(float));
    cudaMemsetAsync(normPtr, 0, (size_t)N_NODES * HEADS * sizeof(float));
    cudaMemsetAsync(cntPtr, 0, N_NODES * sizeof(int));
    cudaMemsetAsync(slotPtr, 0, HEADS * MAX_SLOTS * sizeof(unsigned));

    gemm_kernel<<<(N_NODES + 63) / 64, 256>>>(x, Wm);

    hist_kernel<<<(N_EDGES + 255) / 256, 256>>>(ei);
    scan_kernel<<<1, 1024>>>();
    scatter_kernel<<<(N_EDGES + 255) / 256, 256>>>(ei);

    // 200000 warps -> 25000 blocks of 8 warps, exact fit
    walk_kernel<<<N_EDGES / (SLOTS_PER_WARP * 8), 256>>>(att, out);

    maxreduce_kernel<<<1, 256>>>();

    const long long finElems = (long long)N_NODES * (F_TOT / 4);
    finalize_kernel<<<(unsigned)((finElems + 255) / 256), 256>>>(out);
}

// round 11
// speedup vs baseline: 1.2938x; 1.2938x over previous
#include <cuda_runtime.h>
#include <cstddef>

#define N_NODES 100000
#define N_EDGES 1600000
#define IN_CH   128
#define HEADS   4
#define OUT_CH  32
#define F_TOT   128   // HEADS*OUT_CH
#define MAX_SLOTS 256

// Scratch (static __device__ allocation; runtime alloc forbidden)
__device__ float    g_proj[(size_t)N_NODES * F_TOT];   // 51.2 MB
__device__ float    g_norm[(size_t)N_NODES * HEADS];   // 1.6 MB
__device__ unsigned g_slot[HEADS * MAX_SLOTS];         // hashed per-head max slots
__device__ float    g_hmax[HEADS];                     // final per-head max

// monotone float->uint map (order-preserving); inverse for readback
__device__ __forceinline__ unsigned fmap(float f) {
    unsigned u = __float_as_uint(f);
    return (u & 0x80000000u) ? ~u : (u | 0x80000000u);
}
__device__ __forceinline__ float funmap(unsigned u) {
    return __uint_as_float((u & 0x80000000u) ? (u & 0x7FFFFFFFu) : ~u);
}

// fast tanh: 2 MUFU + few FMA; rel err ~1e-6 (validated: pipeline rel_err 3.7e-7)
__device__ __forceinline__ float fast_tanh(float x) {
    float ax = fabsf(x);
    float e  = __expf(2.0f * ax);             // inf for large ax -> r = 1
    float r  = 1.0f - __fdividef(2.0f, e + 1.0f);
    return copysignf(r, x);
}

// ---------------------------------------------------------------------------
// GEMM v2b: proj = x @ W. 128x128 tile / 256 threads, 8x8 microtile.
// A stored k-major transposed in smem. Row pad = 132 floats (multiple of 4!)
// so float4 accesses at xs_t[k][ty*8] stay 16B-aligned (528 bytes/row).
// Per k-step per thread: 64 FFMA + 4 LDS.128.
// ---------------------------------------------------------------------------
__global__ __launch_bounds__(256) void gemm_kernel(const float* __restrict__ x,
                                                   const float* __restrict__ Wm) {
    __shared__ float xs_t[16][132];    // [k][row], pad 132 (16B-aligned rows)
    __shared__ float ws[16][128];      // [k][col]
    const int t  = threadIdx.x;
    const int tx = t & 15;             // col group
    const int ty = t >> 4;             // row group
    const int rowBase = blockIdx.x * 128;

    float acc[8][8];
#pragma unroll
    for (int i = 0; i < 8; i++)
#pragma unroll
        for (int j = 0; j < 8; j++) acc[i][j] = 0.f;

    // A loader mapping: thread t -> row lr = t>>1 (0..127), k-half lk8=(t&1)*8
    const int lr  = t >> 1;
    const int lk8 = (t & 1) * 8;
    int gr = rowBase + lr;
    if (gr >= N_NODES) gr = N_NODES - 1;   // clamp (dup loads OK, stores guarded)

    for (int kk = 0; kk < IN_CH; kk += 16) {
        // load A: two float4 -> 8 scalars transposed into xs_t
        float4 v0 = *(const float4*)(x + (size_t)gr * IN_CH + kk + lk8);
        float4 v1 = *(const float4*)(x + (size_t)gr * IN_CH + kk + lk8 + 4);
        xs_t[lk8 + 0][lr] = v0.x; xs_t[lk8 + 1][lr] = v0.y;
        xs_t[lk8 + 2][lr] = v0.z; xs_t[lk8 + 3][lr] = v0.w;
        xs_t[lk8 + 4][lr] = v1.x; xs_t[lk8 + 5][lr] = v1.y;
        xs_t[lk8 + 6][lr] = v1.z; xs_t[lk8 + 7][lr] = v1.w;
        // load B: 512 float4 slots, 2 per thread
#pragma unroll
        for (int rep = 0; rep < 2; rep++) {
            int idx = t * 2 + rep;            // 0..511
            int k   = idx >> 5;               // 0..15
            int c4  = (idx & 31) * 4;         // 0..124
            *(float4*)&ws[k][c4] =
                *(const float4*)(Wm + (size_t)(kk + k) * F_TOT + c4);
        }
        __syncthreads();
#pragma unroll
        for (int k = 0; k < 16; k++) {
            float4 a0 = *(float4*)&xs_t[k][ty * 8];
            float4 a1 = *(float4*)&xs_t[k][ty * 8 + 4];
            float4 b0 = *(float4*)&ws[k][tx * 8];
            float4 b1 = *(float4*)&ws[k][tx * 8 + 4];
            float a[8] = {a0.x, a0.y, a0.z, a0.w, a1.x, a1.y, a1.z, a1.w};
            float b[8] = {b0.x, b0.y, b0.z, b0.w, b1.x, b1.y, b1.z, b1.w};
#pragma unroll
            for (int i = 0; i < 8; i++)
#pragma unroll
                for (int j = 0; j < 8; j++)
                    acc[i][j] += a[i] * b[j];
        }
        __syncthreads();
    }

#pragma unroll
    for (int i = 0; i < 8; i++) {
        int r = rowBase + ty * 8 + i;
        if (r < N_NODES) {
            *(float4*)(g_proj + (size_t)r * F_TOT + tx * 8) =
                make_float4(acc[i][0], acc[i][1], acc[i][2], acc[i][3]);
            *(float4*)(g_proj + (size_t)r * F_TOT + tx * 8 + 4) =
                make_float4(acc[i][4], acc[i][5], acc[i][6], acc[i][7]);
        }
    }
}

// ---------------------------------------------------------------------------
// Edge kernel (R6, known-good): one warp per edge, 8 edges/block,
// E/8 = 200000 blocks exactly. Lane L owns channels [4L,4L+4), head = L>>3.
// Unscaled accumulation via red.v4 + norm atomic; per-head global score max
// via block reduce -> hashed atomicMax.
// ---------------------------------------------------------------------------
__global__ __launch_bounds__(256) void edge_kernel(const int* __restrict__ ei,
                                                   const float* __restrict__ att,
                                                   float* __restrict__ out) {
    const int warpInBlk = threadIdx.x >> 5;
    const int lane      = threadIdx.x & 31;
    const int edge      = blockIdx.x * 8 + warpInBlk;

    __shared__ float smax[8][HEADS];

    const int row = __ldg(ei + edge);
    const int col = __ldg(ei + N_EDGES + edge);

    const float4 s4 = *(const float4*)(g_proj + (size_t)row * F_TOT + lane * 4);
    const float4 d4 = *(const float4*)(g_proj + (size_t)col * F_TOT + lane * 4);
    const float4 a4 = *(const float4*)(att + lane * 4);

    float p = fast_tanh(s4.x + d4.x) * a4.x
            + fast_tanh(s4.y + d4.y) * a4.y
            + fast_tanh(s4.z + d4.z) * a4.z
            + fast_tanh(s4.w + d4.w) * a4.w;

    // reduce within each 8-lane head group (all lanes get the sum)
    p += __shfl_xor_sync(0xffffffffu, p, 4);
    p += __shfl_xor_sync(0xffffffffu, p, 2);
    p += __shfl_xor_sync(0xffffffffu, p, 1);

    if ((lane & 7) == 0) smax[warpInBlk][lane >> 3] = p;

    const float w = __expf(p);

    float* op = out + (size_t)col * F_TOT + lane * 4;
    asm volatile("red.global.add.v4.f32 [%0], {%1,%2,%3,%4};"
                 :: "l"(op), "f"(s4.x * w), "f"(s4.y * w),
                    "f"(s4.z * w), "f"(s4.w * w)
                 : "memory");

    if ((lane & 7) == 0)
        atomicAdd(g_norm + (size_t)col * HEADS + (lane >> 3), w);

    __syncthreads();
    if (threadIdx.x < HEADS) {
        float m = smax[0][threadIdx.x];
#pragma unroll
        for (int wb = 1; wb < 8; wb++) m = fmaxf(m, smax[wb][threadIdx.x]);
        atomicMax(&g_slot[threadIdx.x * MAX_SLOTS + (blockIdx.x & (MAX_SLOTS - 1))],
                  fmap(m));
    }
}

// ---------------------------------------------------------------------------
// Reduce hashed max slots -> g_hmax[h]
// ---------------------------------------------------------------------------
__global__ __launch_bounds__(256) void maxreduce_kernel() {
    __shared__ unsigned sm[256];
    const int t = threadIdx.x;
    for (int h = 0; h < HEADS; h++) {
        sm[t] = g_slot[h * MAX_SLOTS + t];
        __syncthreads();
        for (int s = 128; s > 0; s >>= 1) {
            if (t < s) sm[t] = max(sm[t], sm[t + s]);
            __syncthreads();
        }
        if (t == 0) g_hmax[h] = funmap(sm[0]);
        __syncthreads();
    }
}

// ---------------------------------------------------------------------------
// Finalize: exact reference semantics including the 1e-12 clamp:
//   scale = exp(-max_h); out = out_acc*scale / max(norm_acc*scale, 1e-12)
// ---------------------------------------------------------------------------
__global__ __launch_bounds__(256) void finalize_kernel(float* __restrict__ out) {
    size_t i4 = (size_t)blockIdx.x * blockDim.x + threadIdx.x;
    if (i4 >= (size_t)N_NODES * (F_TOT / 4)) return;
    int n = (int)(i4 >> 5);
    int q = (int)(i4 & 31);
    int h = q >> 3;
    float scale = __expf(-g_hmax[h]);
    float nr    = g_norm[(size_t)n * HEADS + h] * scale;
    float inv   = scale / fmaxf(nr, 1e-12f);
    float4 v = *(float4*)(out + i4 * 4);
    v.x *= inv; v.y *= inv; v.z *= inv; v.w *= inv;
    *(float4*)(out + i4 * 4) = v;
}

// ---------------------------------------------------------------------------
extern "C" void kernel_launch(void* const* d_in, const int* in_sizes, int n_in,
                              void* d_out, int out_size) {
    const float* x   = (const float*)d_in[0];
    const int*   ei  = (const int*)d_in[1];    // int32 edge_index [2, E]
    const float* Wm  = (const float*)d_in[2];
    const float* att = (const float*)d_in[3];
    float*       out = (float*)d_out;

    void* normPtr = nullptr;
    void* slotPtr = nullptr;
    cudaGetSymbolAddress(&normPtr, g_norm);
    cudaGetSymbolAddress(&slotPtr, g_slot);

    cudaMemsetAsync(out, 0, (size_t)N_NODES * F_TOT * sizeof(float));
    cudaMemsetAsync(normPtr, 0, (size_t)N_NODES * HEADS * sizeof(float));
    cudaMemsetAsync(slotPtr, 0, HEADS * MAX_SLOTS * sizeof(unsigned));

    gemm_kernel<<<(N_NODES + 127) / 128, 256>>>(x, Wm);

    edge_kernel<<<N_EDGES / 8, 256>>>(ei, att, out);   // 200000 blocks exactly

    maxreduce_kernel<<<1, 256>>>();

    const long long finElems = (long long)N_NODES * (F_TOT / 4);
    finalize_kernel<<<(unsigned)((finElems + 255) / 256), 256>>>(out);
}